// round 11
// baseline (speedup 1.0000x reference)
#include <cuda_runtime.h>
#include <cuda_fp16.h>
#include <math.h>
#include <stdint.h>

// Problem constants (fixed shapes per reference)
#define NMAX 100000
#define EMAX 1600000
#define FIN  256
#define HID  64
#define KCH  10
#define SP   72          // fp16 smem row stride (144B, LDSM conflict-free)
#define PGRID 148        // persistent grid: 1 block/SM guaranteed co-resident

// ---------------- static device scratch (no allocations allowed) -------------
__device__ float g_buf0[NMAX * HID];
__device__ float g_buf1[NMAX * HID];
__device__ float g_buf2[NMAX * HID];

__device__ int   g_deg[NMAX];
__device__ int   g_cnt[NMAX];
__device__ float g_dis[NMAX];
__device__ int   g_excl[NMAX];
__device__ int   g_rowptr[NMAX + 1];
__device__ int   g_cursor[NMAX];
__device__ int   g_blksum[256];
__device__ int2  g_csr[EMAX];          // packed {src, float_as_int(w)}

// global barrier state (only touched in non-skip path)
__device__ volatile unsigned g_gen;
__device__ unsigned g_cntbar;

// Chebyshev nodes x_j = cos((10.5-j)pi/11) (roots of T11), full double precision.
__constant__ double c_seed[KCH + 1] = {
    -0.9898214418809327, -0.9096319953545184, -0.7557495743542583,
    -0.5406408174555976, -0.2817325568414297, 0.0,
     0.2817325568414297,  0.5406408174555976, 0.7557495743542583,
     0.9096319953545184,  0.9898214418809327
};

__device__ __forceinline__ float* bufptr(int i) {
    return (i == 0) ? g_buf0 : ((i == 1) ? g_buf1 : g_buf2);
}

// sense-reversing grid barrier; all blocks of the (co-resident) grid must call.
__device__ __forceinline__ void gbar() {
    __syncthreads();
    if (threadIdx.x == 0) {
        unsigned gen = g_gen;
        __threadfence();
        if (atomicAdd(&g_cntbar, 1u) == gridDim.x - 1) {
            g_cntbar = 0;
            __threadfence();
            g_gen = gen + 1;
        } else {
            while (g_gen == gen) { __nanosleep(32); }
            __threadfence();
        }
    }
    __syncthreads();
}

// ---------------- per-warp Chebyshev coefficients (deterministic) ------------
// Lane j: T_i(x_j) by double recurrence from exact-node constants, times
// temp[j]; smem reduce. coe_i = 2/11 * sum_j acc_i.
// skip iff sum_{i>=1}|coe_i| < 1e-8 (dropping propagation then bounds the
// norm error by ~1e-6 relative — 3 orders under the 1e-3 threshold).
__device__ void warp_coef2(const float* __restrict__ temp,
                           float* s_coe, int* s_skip, int lane)
{
    __shared__ double sred[KCH + 1][KCH + 2];
    double tj = 0.0, x = 0.0;
    if (lane <= KCH) {
        tj = (double)temp[lane];
        x = c_seed[lane];
    }
    double acc[KCH + 1];
    {
        double t0 = 1.0, t1 = x;
        acc[0] = tj;
        acc[1] = x * tj;
        #pragma unroll
        for (int i = 2; i <= KCH; i++) {
            double t2 = 2.0 * x * t1 - t0;
            acc[i] = t2 * tj;
            t0 = t1; t1 = t2;
        }
    }
    if (lane <= KCH) {
        #pragma unroll
        for (int i = 0; i <= KCH; i++) sred[i][lane] = acc[i];
    }
    __syncwarp();
    double c = 0.0;
    if (lane <= KCH) {
        #pragma unroll
        for (int j = 0; j <= KCH; j++) c += sred[lane][j];
        c *= 2.0 / (double)(KCH + 1);
        s_coe[lane] = (float)c;
    }
    double a = (lane >= 1 && lane <= KCH) ? fabs(c) : 0.0;
    #pragma unroll
    for (int off = 16; off > 0; off >>= 1)
        a += __shfl_down_sync(0xffffffffu, a, off);
    if (lane == 0) *s_skip = (a < 1e-8) ? 1 : 0;
    __syncwarp();
}

// ---------------- tensor-core helpers ----------------------------------------
__device__ __forceinline__ uint32_t smem_u32(const void* p) {
    return (uint32_t)__cvta_generic_to_shared(p);
}
__device__ __forceinline__ void ldsm4(uint32_t r[4], uint32_t a) {
    asm volatile("ldmatrix.sync.aligned.m8n8.x4.shared.b16 {%0,%1,%2,%3},[%4];"
        : "=r"(r[0]), "=r"(r[1]), "=r"(r[2]), "=r"(r[3]) : "r"(a));
}
__device__ __forceinline__ void ldsm4t(uint32_t r[4], uint32_t a) {
    asm volatile("ldmatrix.sync.aligned.m8n8.x4.trans.shared.b16 {%0,%1,%2,%3},[%4];"
        : "=r"(r[0]), "=r"(r[1]), "=r"(r[2]), "=r"(r[3]) : "r"(a));
}
__device__ __forceinline__ void mma_f16(float c[4], const uint32_t a[4],
                                        uint32_t b0, uint32_t b1) {
    asm volatile("mma.sync.aligned.m16n8k16.row.col.f32.f16.f16.f32 "
        "{%0,%1,%2,%3},{%4,%5,%6,%7},{%8,%9},{%0,%1,%2,%3};"
        : "+f"(c[0]), "+f"(c[1]), "+f"(c[2]), "+f"(c[3])
        : "r"(a[0]), "r"(a[1]), "r"(a[2]), "r"(a[3]), "r"(b0), "r"(b1));
}
__device__ __forceinline__ uint32_t pack_h2(float2 v) {
    union { __half2 h; uint32_t u; } p;
    p.h = __floats2half2_rn(v.x, v.y);
    return p.u;
}
__device__ __forceinline__ void pack_store(__half* dst, float4 v) {
    union { __half2 h[2]; uint2 u; } p;
    p.h[0] = __floats2half2_rn(v.x, v.y);
    p.h[1] = __floats2half2_rn(v.z, v.w);
    *(uint2*)dst = p.u;
}

// ---------------- MLP (fp16 HMMA, barrier-free mainloop, occ 3) --------------
// out = (sum(temp)/11) * h;  g_buf0 = h (always).
// Block: 128 rows, 8 warps; warp w owns m-rows [16w,16w+16), full N=64.
// smem: W1T [256k][SP] fp16 | W2 [64][SP] fp16 | H strips [128][SP] fp16.
// ONE block-wide barrier (after W staging); A loads go global->regs directly.
#define SM_W1 0
#define SM_W2 (256 * SP * 2)                 // 36864
#define SM_H  (SM_W2 + 64 * SP * 2)          // 46080
#define SMEM_MLP (SM_H + 128 * SP * 2)       // 64512

__global__ __launch_bounds__(256, 3) void mlp_tc_main(
    const float* __restrict__ x,
    const float* __restrict__ W1, const float* __restrict__ b1,
    const float* __restrict__ W2, const float* __restrict__ b2,
    const float* __restrict__ temp,
    int n, float* __restrict__ out)
{
    extern __shared__ char sm[];
    __half* sW1 = (__half*)(sm + SM_W1);   // [256][SP] k-major
    __half* sW2 = (__half*)(sm + SM_W2);   // [64][SP]  k-major
    __half* sH  = (__half*)(sm + SM_H);    // [128][SP] per-warp strips
    __shared__ float s_c0h;

    const int tid = threadIdx.x, lane = tid & 31, warp = tid >> 5;
    const int row0 = blockIdx.x * 128;
    const int m0 = warp * 16;

    if (tid == 0) {
        double s = 0.0;
        #pragma unroll
        for (int j = 0; j <= KCH; j++) s += (double)temp[j];
        s_c0h = (float)(s / (double)(KCH + 1));
    }

    // ---- stage W1 [256][64] and W2 [64][64] fp32 -> fp16 smem (k-major) ----
    {
        #pragma unroll
        for (int it = 0; it < 16; it++) {
            int f = tid + it * 256;            // float4 index, 4096 total
            int kr = f >> 4, n4 = (f & 15) * 4;
            pack_store(sW1 + kr * SP + n4, *(const float4*)(W1 + (size_t)kr * HID + n4));
        }
        #pragma unroll
        for (int it = 0; it < 4; it++) {
            int f = tid + it * 256;            // 1024 total
            int kr = f >> 4, n4 = (f & 15) * 4;
            pack_store(sW2 + kr * SP + n4, *(const float4*)(W2 + (size_t)kr * HID + n4));
        }
    }
    __syncthreads();   // the ONLY block-wide barrier

    // B ldsm4t lane addressing (k-major smem)
    const int brow = (lane & 7) + ((lane >> 3) & 1) * 8;
    const int bcol = (lane >> 4) * 8;
    const uint32_t bW1 = smem_u32(sW1) + (uint32_t)(brow * SP + bcol) * 2;
    const uint32_t bW2 = smem_u32(sW2) + (uint32_t)(brow * SP + bcol) * 2;

    // A direct-load lane addressing: row r = m0 + lane/4, col pair c = (lane%4)*2
    const int rA = m0 + (lane >> 2);
    const int cA = (lane & 3) * 2;
    const bool v0 = (row0 + rA) < n;
    const bool v1 = (row0 + rA + 8) < n;
    const float* xr0 = x + (size_t)(row0 + rA) * FIN + cA;
    const float* xr8 = xr0 + 8 * FIN;
    const float2 fz = make_float2(0.f, 0.f);

    float c1[8][4];
    #pragma unroll
    for (int i = 0; i < 8; i++)
        #pragma unroll
        for (int j = 0; j < 4; j++) c1[i][j] = 0.f;

    // ---- GEMM1: K=256 as 16 independent k-fragments, no barriers ----
    #pragma unroll 4
    for (int kf = 0; kf < 16; kf++) {
        int k0 = kf * 16;
        float2 f0 = v0 ? *(const float2*)(xr0 + k0)     : fz;
        float2 f1 = v1 ? *(const float2*)(xr8 + k0)     : fz;
        float2 f2 = v0 ? *(const float2*)(xr0 + k0 + 8) : fz;
        float2 f3 = v1 ? *(const float2*)(xr8 + k0 + 8) : fz;
        uint32_t a[4];
        a[0] = pack_h2(f0);
        a[1] = pack_h2(f1);
        a[2] = pack_h2(f2);
        a[3] = pack_h2(f3);
        uint32_t kadd = (uint32_t)(kf * 16 * SP) * 2;
        #pragma unroll
        for (int ntp = 0; ntp < 4; ntp++) {
            uint32_t b[4];
            ldsm4t(b, bW1 + kadd + ntp * 32);
            mma_f16(c1[2 * ntp],     a, b[0], b[1]);
            mma_f16(c1[2 * ntp + 1], a, b[2], b[3]);
        }
    }

    // ---- H = relu(c1 + b1) -> per-warp smem strip (warp-local only) ---------
    const int g = lane >> 2, tq = lane & 3;
    {
        const float2* b1f2 = (const float2*)b1;
        __half* hs = sH + (size_t)m0 * SP;
        #pragma unroll
        for (int nt = 0; nt < 8; nt++) {
            float2 bb = b1f2[nt * 4 + tq];
            int col = nt * 8 + tq * 2;
            float v0h = fmaxf(c1[nt][0] + bb.x, 0.f);
            float v1h = fmaxf(c1[nt][1] + bb.y, 0.f);
            float v2h = fmaxf(c1[nt][2] + bb.x, 0.f);
            float v3h = fmaxf(c1[nt][3] + bb.y, 0.f);
            *(__half2*)(hs + g * SP + col)       = __floats2half2_rn(v0h, v1h);
            *(__half2*)(hs + (g + 8) * SP + col) = __floats2half2_rn(v2h, v3h);
        }
    }
    __syncwarp();

    // ---- GEMM2: H[m0..m0+16][64] @ W2 (per-warp, ldsm from own strip) -------
    const uint32_t aH = smem_u32(sH + (size_t)(m0 + (lane & 15)) * SP)
                        + (uint32_t)(lane >> 4) * 16;
    float c2[8][4];
    #pragma unroll
    for (int i = 0; i < 8; i++)
        #pragma unroll
        for (int j = 0; j < 4; j++) c2[i][j] = 0.f;

    #pragma unroll
    for (int ks = 0; ks < 4; ks++) {
        uint32_t a[4];
        ldsm4(a, aH + ks * 32);
        uint32_t kadd = (uint32_t)(ks * 16 * SP) * 2;
        #pragma unroll
        for (int ntp = 0; ntp < 4; ntp++) {
            uint32_t b[4];
            ldsm4t(b, bW2 + kadd + ntp * 32);
            mma_f16(c2[2 * ntp],     a, b[0], b[1]);
            mma_f16(c2[2 * ntp + 1], a, b[2], b[3]);
        }
    }

    // ---- epilogue: h2 = c2 + b2;  g_buf0 = h2;  out = c0h*h2 ----------------
    {
        const float2* b2f2 = (const float2*)b2;
        float c0h = s_c0h;
        #pragma unroll
        for (int nt = 0; nt < 8; nt++) {
            float2 bb = b2f2[nt * 4 + tq];
            int col = nt * 8 + tq * 2;
            int r0 = row0 + m0 + g, r1 = r0 + 8;
            if (r0 < n) {
                float2 h2 = make_float2(c2[nt][0] + bb.x, c2[nt][1] + bb.y);
                *(float2*)(g_buf0 + (size_t)r0 * HID + col) = h2;
                *(float2*)(out + (size_t)r0 * HID + col) = make_float2(c0h * h2.x, c0h * h2.y);
            }
            if (r1 < n) {
                float2 h2 = make_float2(c2[nt][2] + bb.x, c2[nt][3] + bb.y);
                *(float2*)(g_buf0 + (size_t)r1 * HID + col) = h2;
                *(float2*)(out + (size_t)r1 * HID + col) = make_float2(c0h * h2.x, c0h * h2.y);
            }
        }
    }
}

// ---------------- CSR edge accumulation --------------------------------------
__device__ __forceinline__ void prop_accum(const float2* __restrict__ v2,
                                           int s, int e, int lane,
                                           float& ax, float& ay)
{
    int i = s;
    for (; i + 4 <= e; i += 4) {
        int2 e0 = g_csr[i + 0], e1 = g_csr[i + 1];
        int2 e2 = g_csr[i + 2], e3 = g_csr[i + 3];
        float2 x0 = v2[e0.x * 32 + lane];
        float2 x1 = v2[e1.x * 32 + lane];
        float2 x2 = v2[e2.x * 32 + lane];
        float2 x3 = v2[e3.x * 32 + lane];
        float w0 = __int_as_float(e0.y), w1 = __int_as_float(e1.y);
        float w2 = __int_as_float(e2.y), w3 = __int_as_float(e3.y);
        ax = fmaf(w0, x0.x, ax); ay = fmaf(w0, x0.y, ay);
        ax = fmaf(w1, x1.x, ax); ay = fmaf(w1, x1.y, ay);
        ax = fmaf(w2, x2.x, ax); ay = fmaf(w2, x2.y, ay);
        ax = fmaf(w3, x3.x, ax); ay = fmaf(w3, x3.y, ay);
    }
    for (; i < e; i++) {
        int2 e0 = g_csr[i];
        float w0 = __int_as_float(e0.y);
        float2 x0 = v2[e0.x * 32 + lane];
        ax = fmaf(w0, x0.x, ax); ay = fmaf(w0, x0.y, ay);
    }
}

// ---------------- fused persistent preprocessing + propagation ---------------
// Computes coefficients locally (deterministic, identical per block) and
// self-gates: exits immediately when propagation is numerically negligible.
__global__ __launch_bounds__(256) void prep_prop_persist(
    const int* __restrict__ ei, const float* __restrict__ temp,
    int e, int n, float2* __restrict__ out)
{
    __shared__ int wsum[8];
    __shared__ int s2[256];
    __shared__ float s_coe[KCH + 1];
    __shared__ int s_skip;
    const int tid = threadIdx.x;

    if (tid < 32) warp_coef2(temp, s_coe, &s_skip, tid);
    __syncthreads();
    if (s_skip) return;

    const int gtid = blockIdx.x * 256 + tid;
    const int gsz = gridDim.x * 256;

    // phase 0: zero
    for (int i = gtid; i < n; i += gsz) { g_deg[i] = 0; g_cnt[i] = 0; }
    gbar();
    // phase 1: histogram
    for (int i = gtid; i < e; i += gsz) {
        int r = ei[i];
        int c = ei[(size_t)e + i];
        if ((unsigned)r < (unsigned)n) atomicAdd(&g_deg[r], 1);
        if ((unsigned)c < (unsigned)n) atomicAdd(&g_cnt[c], 1);
    }
    gbar();
    // phase 2a: per-1024-chunk exclusive scan of g_cnt + fused dis
    int nchunk = (n + 1023) >> 10;
    for (int chunk = blockIdx.x; chunk < nchunk; chunk += gridDim.x) {
        int lane = tid & 31, wid = tid >> 5;
        int base = chunk * 1024 + tid * 4;
        int v[4];
        #pragma unroll
        for (int j = 0; j < 4; j++) {
            int idx = base + j;
            v[j] = (idx < n) ? g_cnt[idx] : 0;
            if (idx < n) {
                int d = g_deg[idx];
                g_dis[idx] = (d > 0) ? rsqrtf((float)d) : 0.f;
            }
        }
        int tsum = v[0] + v[1] + v[2] + v[3];
        int sc = tsum;
        #pragma unroll
        for (int off = 1; off < 32; off <<= 1) {
            int t = __shfl_up_sync(0xffffffffu, sc, off);
            if (lane >= off) sc += t;
        }
        if (lane == 31) wsum[wid] = sc;
        __syncthreads();
        if (tid == 0) {
            int a = 0;
            #pragma unroll
            for (int i = 0; i < 8; i++) { int t = wsum[i]; wsum[i] = a; a += t; }
        }
        __syncthreads();
        int run = (sc - tsum) + wsum[wid];
        #pragma unroll
        for (int j = 0; j < 4; j++) {
            if (base + j < n) g_excl[base + j] = run;
            run += v[j];
        }
        if (tid == 255) g_blksum[chunk] = run;
        __syncthreads();
    }
    gbar();
    // phase 2b: scan chunk sums (block 0)
    if (blockIdx.x == 0) {
        if (tid < nchunk) s2[tid] = g_blksum[tid];
        __syncthreads();
        if (tid == 0) {
            int a = 0;
            for (int i = 0; i < nchunk; i++) { int t = s2[i]; s2[i] = a; a += t; }
        }
        __syncthreads();
        if (tid < nchunk) g_blksum[tid] = s2[tid];
    }
    gbar();
    // phase 2c: rowptr/cursor
    for (int i = gtid; i < n; i += gsz) {
        int v = g_excl[i] + g_blksum[i >> 10];
        g_rowptr[i] = v;
        g_cursor[i] = v;
    }
    if (gtid == 0) g_rowptr[n] = e;
    gbar();
    // phase 3: scatter into CSR
    for (int i = gtid; i < e; i += gsz) {
        int r = ei[i];
        int c = ei[(size_t)e + i];
        if ((unsigned)r >= (unsigned)n || (unsigned)c >= (unsigned)n) continue;
        float w = -g_dis[r] * g_dis[c];
        int pos = atomicAdd(&g_cursor[c], 1);
        g_csr[pos] = make_int2(r, __float_as_int(w));
    }
    gbar();

    // ---- propagation: Chebyshev recurrence ----
    const int lane = tid & 31;
    const int gw = blockIdx.x * 8 + (tid >> 5);
    const int gwn = gridDim.x * 8;

    // step 1: Tx1 = prop(h); out += coe1 * Tx1
    {
        const float2* v2 = (const float2*)g_buf0;
        float c1 = s_coe[1];
        for (int dst0 = gw * 4; dst0 < n; dst0 += gwn * 4) {
            #pragma unroll
            for (int t = 0; t < 4; t++) {
                int dst = dst0 + t;
                if (dst >= n) break;
                int s = g_rowptr[dst], e2 = g_rowptr[dst + 1];
                float ax = 0.f, ay = 0.f;
                prop_accum(v2, s, e2, lane, ax, ay);
                int idx = dst * 32 + lane;
                ((float2*)g_buf1)[idx] = make_float2(ax, ay);
                float2 o = out[idx];
                o.x = fmaf(c1, ax, o.x);
                o.y = fmaf(c1, ay, o.y);
                out[idx] = o;
            }
        }
    }
    // steps 2..K
    int i0 = 0, i1 = 1;
    for (int i = 2; i <= KCH; i++) {
        gbar();
        int i2 = 3 - i0 - i1;
        const float2* v2 = (const float2*)bufptr(i1);
        const float2* t0 = (const float2*)bufptr(i0);
        float2* t2 = (float2*)bufptr(i2);
        float coe = s_coe[i];
        for (int dst0 = gw * 4; dst0 < n; dst0 += gwn * 4) {
            #pragma unroll
            for (int t = 0; t < 4; t++) {
                int dst = dst0 + t;
                if (dst >= n) break;
                int s = g_rowptr[dst], e2 = g_rowptr[dst + 1];
                float ax = 0.f, ay = 0.f;
                prop_accum(v2, s, e2, lane, ax, ay);
                int idx = dst * 32 + lane;
                float2 p0 = t0[idx];
                float2 nt = make_float2(2.f * ax - p0.x, 2.f * ay - p0.y);
                t2[idx] = nt;
                float2 o = out[idx];
                o.x = fmaf(coe, nt.x, o.x);
                o.y = fmaf(coe, nt.y, o.y);
                out[idx] = o;
            }
        }
        i0 = i1; i1 = i2;
    }
}

// ---------------- launch ------------------------------------------------------
extern "C" void kernel_launch(void* const* d_in, const int* in_sizes, int n_in,
                              void* d_out, int out_size)
{
    const float* x    = (const float*)d_in[0];
    const int*   ei   = (const int*)d_in[1];
    const float* W1   = (const float*)d_in[2];
    const float* b1   = (const float*)d_in[3];
    const float* W2   = (const float*)d_in[4];
    const float* b2   = (const float*)d_in[5];
    const float* temp = (const float*)d_in[6];
    float*       out  = (float*)d_out;

    int n = in_sizes[0] / FIN;   // 100000
    int e = in_sizes[1] / 2;     // 1600000

    static int attr_done = 0;
    if (!attr_done) {
        cudaFuncSetAttribute(mlp_tc_main,
                             cudaFuncAttributeMaxDynamicSharedMemorySize, SMEM_MLP);
        attr_done = 1;
    }

    mlp_tc_main<<<(n + 127) / 128, 256, SMEM_MLP>>>(x, W1, b1, W2, b2, temp, n, out);
    prep_prop_persist<<<PGRID, 256>>>(ei, temp, e, n, (float2*)out);
}

// round 12
// speedup vs baseline: 1.1679x; 1.1679x over previous
#include <cuda_runtime.h>
#include <cuda_fp16.h>
#include <math.h>
#include <stdint.h>

// Problem constants (fixed shapes per reference)
#define NMAX 100000
#define EMAX 1600000
#define FIN  256
#define HID  64
#define KCH  10
#define SP   72          // fp16 smem row stride (144B, LDSM conflict-free)
#define PGRID 148        // persistent grid: 1 block/SM guaranteed co-resident

// ---------------- static device scratch (no allocations allowed) -------------
__device__ float g_buf0[NMAX * HID];
__device__ float g_buf1[NMAX * HID];
__device__ float g_buf2[NMAX * HID];

__device__ int   g_deg[NMAX];
__device__ int   g_cnt[NMAX];
__device__ float g_dis[NMAX];
__device__ int   g_excl[NMAX];
__device__ int   g_rowptr[NMAX + 1];
__device__ int   g_cursor[NMAX];
__device__ int   g_blksum[256];
__device__ int2  g_csr[EMAX];          // packed {src, float_as_int(w)}

// global barrier state (only touched in non-skip path)
__device__ volatile unsigned g_gen;
__device__ unsigned g_cntbar;

// Chebyshev nodes x_j = cos((10.5-j)pi/11) (roots of T11), full double precision.
__constant__ double c_seed[KCH + 1] = {
    -0.9898214418809327, -0.9096319953545184, -0.7557495743542583,
    -0.5406408174555976, -0.2817325568414297, 0.0,
     0.2817325568414297,  0.5406408174555976, 0.7557495743542583,
     0.9096319953545184,  0.9898214418809327
};

__device__ __forceinline__ float* bufptr(int i) {
    return (i == 0) ? g_buf0 : ((i == 1) ? g_buf1 : g_buf2);
}

// sense-reversing grid barrier; all blocks of the (co-resident) grid must call.
__device__ __forceinline__ void gbar() {
    __syncthreads();
    if (threadIdx.x == 0) {
        unsigned gen = g_gen;
        __threadfence();
        if (atomicAdd(&g_cntbar, 1u) == gridDim.x - 1) {
            g_cntbar = 0;
            __threadfence();
            g_gen = gen + 1;
        } else {
            while (g_gen == gen) { __nanosleep(32); }
            __threadfence();
        }
    }
    __syncthreads();
}

// ---------------- per-warp Chebyshev coefficients (deterministic) ------------
// Lane j: T_i(x_j) by double recurrence from exact-node constants, times
// temp[j]; smem reduce. coe_i = 2/11 * sum_j acc_i.
// skip iff sum_{i>=1}|coe_i| < 1e-8 (dropping propagation then bounds the
// norm error by ~1e-6 relative — 3 orders under the 1e-3 threshold).
__device__ void warp_coef2(const float* __restrict__ temp,
                           float* s_coe, int* s_skip, int lane)
{
    __shared__ double sred[KCH + 1][KCH + 2];
    double tj = 0.0, x = 0.0;
    if (lane <= KCH) {
        tj = (double)temp[lane];
        x = c_seed[lane];
    }
    double acc[KCH + 1];
    {
        double t0 = 1.0, t1 = x;
        acc[0] = tj;
        acc[1] = x * tj;
        #pragma unroll
        for (int i = 2; i <= KCH; i++) {
            double t2 = 2.0 * x * t1 - t0;
            acc[i] = t2 * tj;
            t0 = t1; t1 = t2;
        }
    }
    if (lane <= KCH) {
        #pragma unroll
        for (int i = 0; i <= KCH; i++) sred[i][lane] = acc[i];
    }
    __syncwarp();
    double c = 0.0;
    if (lane <= KCH) {
        #pragma unroll
        for (int j = 0; j <= KCH; j++) c += sred[lane][j];
        c *= 2.0 / (double)(KCH + 1);
        s_coe[lane] = (float)c;
    }
    double a = (lane >= 1 && lane <= KCH) ? fabs(c) : 0.0;
    #pragma unroll
    for (int off = 16; off > 0; off >>= 1)
        a += __shfl_down_sync(0xffffffffu, a, off);
    if (lane == 0) *s_skip = (a < 1e-8) ? 1 : 0;
    __syncwarp();
}

// ---------------- tensor-core helpers ----------------------------------------
__device__ __forceinline__ uint32_t smem_u32(const void* p) {
    return (uint32_t)__cvta_generic_to_shared(p);
}
__device__ __forceinline__ void ldsm4(uint32_t r[4], uint32_t a) {
    asm volatile("ldmatrix.sync.aligned.m8n8.x4.shared.b16 {%0,%1,%2,%3},[%4];"
        : "=r"(r[0]), "=r"(r[1]), "=r"(r[2]), "=r"(r[3]) : "r"(a));
}
__device__ __forceinline__ void ldsm4t(uint32_t r[4], uint32_t a) {
    asm volatile("ldmatrix.sync.aligned.m8n8.x4.trans.shared.b16 {%0,%1,%2,%3},[%4];"
        : "=r"(r[0]), "=r"(r[1]), "=r"(r[2]), "=r"(r[3]) : "r"(a));
}
__device__ __forceinline__ void mma_f16(float c[4], const uint32_t a[4],
                                        uint32_t b0, uint32_t b1) {
    asm volatile("mma.sync.aligned.m16n8k16.row.col.f32.f16.f16.f32 "
        "{%0,%1,%2,%3},{%4,%5,%6,%7},{%8,%9},{%0,%1,%2,%3};"
        : "+f"(c[0]), "+f"(c[1]), "+f"(c[2]), "+f"(c[3])
        : "r"(a[0]), "r"(a[1]), "r"(a[2]), "r"(a[3]), "r"(b0), "r"(b1));
}
__device__ __forceinline__ uint32_t pack_h2(float2 v) {
    union { __half2 h; uint32_t u; } p;
    p.h = __floats2half2_rn(v.x, v.y);
    return p.u;
}
__device__ __forceinline__ void pack_store(__half* dst, float4 v) {
    union { __half2 h[2]; uint2 u; } p;
    p.h[0] = __floats2half2_rn(v.x, v.y);
    p.h[1] = __floats2half2_rn(v.z, v.w);
    *(uint2*)dst = p.u;
}

// ---------------- MLP (fp16 HMMA, warp-local staged A, coalesced LDG) --------
// out = (sum(temp)/11) * h;  g_buf0 = h (always).
// Block: 128 rows, 8 warps; warp w owns m-rows [16w,16w+16), full N=64.
// smem: W1T [256k][SP] fp16 | W2 [64][SP] fp16 | strips [128][SP] fp16
//       (strips serve as per-warp X-chunk staging during GEMM1, then as H).
// ONE block-wide barrier (after W staging); X loads are row-contiguous
// (32 lanes x 8B = 256B per LDG.64, 2 lines) into the warp's own strip.
#define SM_W1 0
#define SM_W2 (256 * SP * 2)                 // 36864
#define SM_H  (SM_W2 + 64 * SP * 2)          // 46080
#define SMEM_MLP (SM_H + 128 * SP * 2)       // 64512

__global__ __launch_bounds__(256, 2) void mlp_tc_main(
    const float* __restrict__ x,
    const float* __restrict__ W1, const float* __restrict__ b1,
    const float* __restrict__ W2, const float* __restrict__ b2,
    const float* __restrict__ temp,
    int n, float* __restrict__ out)
{
    extern __shared__ char sm[];
    __half* sW1 = (__half*)(sm + SM_W1);   // [256][SP] k-major
    __half* sW2 = (__half*)(sm + SM_W2);   // [64][SP]  k-major
    __half* sH  = (__half*)(sm + SM_H);    // [128][SP] per-warp strips
    __shared__ float s_c0h;

    const int tid = threadIdx.x, lane = tid & 31, warp = tid >> 5;
    const int row0 = blockIdx.x * 128;
    const int m0 = warp * 16;

    if (tid == 0) {
        double s = 0.0;
        #pragma unroll
        for (int j = 0; j <= KCH; j++) s += (double)temp[j];
        s_c0h = (float)(s / (double)(KCH + 1));
    }

    // ---- stage W1 [256][64] and W2 [64][64] fp32 -> fp16 smem (k-major) ----
    {
        #pragma unroll
        for (int it = 0; it < 16; it++) {
            int f = tid + it * 256;            // float4 index, 4096 total
            int kr = f >> 4, n4 = (f & 15) * 4;
            pack_store(sW1 + kr * SP + n4, *(const float4*)(W1 + (size_t)kr * HID + n4));
        }
        #pragma unroll
        for (int it = 0; it < 4; it++) {
            int f = tid + it * 256;            // 1024 total
            int kr = f >> 4, n4 = (f & 15) * 4;
            pack_store(sW2 + kr * SP + n4, *(const float4*)(W2 + (size_t)kr * HID + n4));
        }
    }
    __syncthreads();   // the ONLY block-wide barrier

    // B ldsm4t lane addressing (k-major smem)
    const int brow = (lane & 7) + ((lane >> 3) & 1) * 8;
    const int bcol = (lane >> 4) * 8;
    const uint32_t bW1 = smem_u32(sW1) + (uint32_t)(brow * SP + bcol) * 2;
    const uint32_t bW2 = smem_u32(sW2) + (uint32_t)(brow * SP + bcol) * 2;

    // per-warp strip (X staging during GEMM1, H afterwards)
    __half* strip = sH + (size_t)m0 * SP;
    // A ldsm lane addressing within own strip: row = lane%16, 16B-half = lane/16
    const uint32_t aBase = smem_u32(strip + (size_t)(lane & 15) * SP)
                           + (uint32_t)(lane >> 4) * 16;

    // X row-contiguous loader: per chunk, row r cols [lane*2, lane*2+1]
    const float* xw = x + (size_t)(row0 + m0) * FIN + lane * 2;
    // number of valid rows in this warp's 16-row slice
    const int vrows = min(16, max(0, n - (row0 + m0)));

    float c1[8][4];
    #pragma unroll
    for (int i = 0; i < 8; i++)
        #pragma unroll
        for (int j = 0; j < 4; j++) c1[i][j] = 0.f;

    // ---- GEMM1: K=256 in 4 chunks of 64; warp-local staging, no block sync --
    #pragma unroll
    for (int c = 0; c < 4; c++) {
        // load 16 rows x 64 cols, row-contiguous (2 lines per LDG.64)
        float2 v[16];
        if (vrows == 16) {
            #pragma unroll
            for (int r = 0; r < 16; r++)
                v[r] = *(const float2*)(xw + (size_t)r * FIN + c * 64);
        } else {
            #pragma unroll
            for (int r = 0; r < 16; r++)
                v[r] = (r < vrows) ? *(const float2*)(xw + (size_t)r * FIN + c * 64)
                                   : make_float2(0.f, 0.f);
        }
        // pack -> own strip (STS.32, conflict-free: 32 lanes x 4B consecutive)
        #pragma unroll
        for (int r = 0; r < 16; r++)
            *(uint32_t*)((char*)(strip + (size_t)r * SP + lane * 2)) = pack_h2(v[r]);
        __syncwarp();
        // MMA over this chunk
        #pragma unroll
        for (int ks = 0; ks < 4; ks++) {
            uint32_t a[4];
            ldsm4(a, aBase + ks * 32);
            uint32_t kadd = (uint32_t)((c * 64 + ks * 16) * SP) * 2;
            #pragma unroll
            for (int ntp = 0; ntp < 4; ntp++) {
                uint32_t b[4];
                ldsm4t(b, bW1 + kadd + ntp * 32);
                mma_f16(c1[2 * ntp],     a, b[0], b[1]);
                mma_f16(c1[2 * ntp + 1], a, b[2], b[3]);
            }
        }
        __syncwarp();   // strip reuse fence for next chunk
    }

    // ---- H = relu(c1 + b1) -> own strip (warp-local only) -------------------
    const int g = lane >> 2, tq = lane & 3;
    {
        const float2* b1f2 = (const float2*)b1;
        #pragma unroll
        for (int nt = 0; nt < 8; nt++) {
            float2 bb = b1f2[nt * 4 + tq];
            int col = nt * 8 + tq * 2;
            float v0h = fmaxf(c1[nt][0] + bb.x, 0.f);
            float v1h = fmaxf(c1[nt][1] + bb.y, 0.f);
            float v2h = fmaxf(c1[nt][2] + bb.x, 0.f);
            float v3h = fmaxf(c1[nt][3] + bb.y, 0.f);
            *(__half2*)(strip + (size_t)g * SP + col)       = __floats2half2_rn(v0h, v1h);
            *(__half2*)(strip + (size_t)(g + 8) * SP + col) = __floats2half2_rn(v2h, v3h);
        }
    }
    __syncwarp();

    // ---- GEMM2: H[16][64] @ W2 (per-warp, ldsm from own strip) --------------
    float c2[8][4];
    #pragma unroll
    for (int i = 0; i < 8; i++)
        #pragma unroll
        for (int j = 0; j < 4; j++) c2[i][j] = 0.f;

    #pragma unroll
    for (int ks = 0; ks < 4; ks++) {
        uint32_t a[4];
        ldsm4(a, aBase + ks * 32);
        uint32_t kadd = (uint32_t)(ks * 16 * SP) * 2;
        #pragma unroll
        for (int ntp = 0; ntp < 4; ntp++) {
            uint32_t b[4];
            ldsm4t(b, bW2 + kadd + ntp * 32);
            mma_f16(c2[2 * ntp],     a, b[0], b[1]);
            mma_f16(c2[2 * ntp + 1], a, b[2], b[3]);
        }
    }

    // ---- epilogue: h2 = c2 + b2;  g_buf0 = h2;  out = c0h*h2 ----------------
    {
        const float2* b2f2 = (const float2*)b2;
        float c0h = s_c0h;
        #pragma unroll
        for (int nt = 0; nt < 8; nt++) {
            float2 bb = b2f2[nt * 4 + tq];
            int col = nt * 8 + tq * 2;
            int r0 = row0 + m0 + g, r1 = r0 + 8;
            if (r0 < n) {
                float2 h2 = make_float2(c2[nt][0] + bb.x, c2[nt][1] + bb.y);
                *(float2*)(g_buf0 + (size_t)r0 * HID + col) = h2;
                *(float2*)(out + (size_t)r0 * HID + col) = make_float2(c0h * h2.x, c0h * h2.y);
            }
            if (r1 < n) {
                float2 h2 = make_float2(c2[nt][2] + bb.x, c2[nt][3] + bb.y);
                *(float2*)(g_buf0 + (size_t)r1 * HID + col) = h2;
                *(float2*)(out + (size_t)r1 * HID + col) = make_float2(c0h * h2.x, c0h * h2.y);
            }
        }
    }
}

// ---------------- CSR edge accumulation --------------------------------------
__device__ __forceinline__ void prop_accum(const float2* __restrict__ v2,
                                           int s, int e, int lane,
                                           float& ax, float& ay)
{
    int i = s;
    for (; i + 4 <= e; i += 4) {
        int2 e0 = g_csr[i + 0], e1 = g_csr[i + 1];
        int2 e2 = g_csr[i + 2], e3 = g_csr[i + 3];
        float2 x0 = v2[e0.x * 32 + lane];
        float2 x1 = v2[e1.x * 32 + lane];
        float2 x2 = v2[e2.x * 32 + lane];
        float2 x3 = v2[e3.x * 32 + lane];
        float w0 = __int_as_float(e0.y), w1 = __int_as_float(e1.y);
        float w2 = __int_as_float(e2.y), w3 = __int_as_float(e3.y);
        ax = fmaf(w0, x0.x, ax); ay = fmaf(w0, x0.y, ay);
        ax = fmaf(w1, x1.x, ax); ay = fmaf(w1, x1.y, ay);
        ax = fmaf(w2, x2.x, ax); ay = fmaf(w2, x2.y, ay);
        ax = fmaf(w3, x3.x, ax); ay = fmaf(w3, x3.y, ay);
    }
    for (; i < e; i++) {
        int2 e0 = g_csr[i];
        float w0 = __int_as_float(e0.y);
        float2 x0 = v2[e0.x * 32 + lane];
        ax = fmaf(w0, x0.x, ax); ay = fmaf(w0, x0.y, ay);
    }
}

// ---------------- fused persistent preprocessing + propagation ---------------
// Computes coefficients locally (deterministic, identical per block) and
// self-gates: exits immediately when propagation is numerically negligible.
__global__ __launch_bounds__(256) void prep_prop_persist(
    const int* __restrict__ ei, const float* __restrict__ temp,
    int e, int n, float2* __restrict__ out)
{
    __shared__ int wsum[8];
    __shared__ int s2[256];
    __shared__ float s_coe[KCH + 1];
    __shared__ int s_skip;
    const int tid = threadIdx.x;

    if (tid < 32) warp_coef2(temp, s_coe, &s_skip, tid);
    __syncthreads();
    if (s_skip) return;

    const int gtid = blockIdx.x * 256 + tid;
    const int gsz = gridDim.x * 256;

    // phase 0: zero
    for (int i = gtid; i < n; i += gsz) { g_deg[i] = 0; g_cnt[i] = 0; }
    gbar();
    // phase 1: histogram
    for (int i = gtid; i < e; i += gsz) {
        int r = ei[i];
        int c = ei[(size_t)e + i];
        if ((unsigned)r < (unsigned)n) atomicAdd(&g_deg[r], 1);
        if ((unsigned)c < (unsigned)n) atomicAdd(&g_cnt[c], 1);
    }
    gbar();
    // phase 2a: per-1024-chunk exclusive scan of g_cnt + fused dis
    int nchunk = (n + 1023) >> 10;
    for (int chunk = blockIdx.x; chunk < nchunk; chunk += gridDim.x) {
        int lane = tid & 31, wid = tid >> 5;
        int base = chunk * 1024 + tid * 4;
        int v[4];
        #pragma unroll
        for (int j = 0; j < 4; j++) {
            int idx = base + j;
            v[j] = (idx < n) ? g_cnt[idx] : 0;
            if (idx < n) {
                int d = g_deg[idx];
                g_dis[idx] = (d > 0) ? rsqrtf((float)d) : 0.f;
            }
        }
        int tsum = v[0] + v[1] + v[2] + v[3];
        int sc = tsum;
        #pragma unroll
        for (int off = 1; off < 32; off <<= 1) {
            int t = __shfl_up_sync(0xffffffffu, sc, off);
            if (lane >= off) sc += t;
        }
        if (lane == 31) wsum[wid] = sc;
        __syncthreads();
        if (tid == 0) {
            int a = 0;
            #pragma unroll
            for (int i = 0; i < 8; i++) { int t = wsum[i]; wsum[i] = a; a += t; }
        }
        __syncthreads();
        int run = (sc - tsum) + wsum[wid];
        #pragma unroll
        for (int j = 0; j < 4; j++) {
            if (base + j < n) g_excl[base + j] = run;
            run += v[j];
        }
        if (tid == 255) g_blksum[chunk] = run;
        __syncthreads();
    }
    gbar();
    // phase 2b: scan chunk sums (block 0)
    if (blockIdx.x == 0) {
        if (tid < nchunk) s2[tid] = g_blksum[tid];
        __syncthreads();
        if (tid == 0) {
            int a = 0;
            for (int i = 0; i < nchunk; i++) { int t = s2[i]; s2[i] = a; a += t; }
        }
        __syncthreads();
        if (tid < nchunk) g_blksum[tid] = s2[tid];
    }
    gbar();
    // phase 2c: rowptr/cursor
    for (int i = gtid; i < n; i += gsz) {
        int v = g_excl[i] + g_blksum[i >> 10];
        g_rowptr[i] = v;
        g_cursor[i] = v;
    }
    if (gtid == 0) g_rowptr[n] = e;
    gbar();
    // phase 3: scatter into CSR
    for (int i = gtid; i < e; i += gsz) {
        int r = ei[i];
        int c = ei[(size_t)e + i];
        if ((unsigned)r >= (unsigned)n || (unsigned)c >= (unsigned)n) continue;
        float w = -g_dis[r] * g_dis[c];
        int pos = atomicAdd(&g_cursor[c], 1);
        g_csr[pos] = make_int2(r, __float_as_int(w));
    }
    gbar();

    // ---- propagation: Chebyshev recurrence ----
    const int lane = tid & 31;
    const int gw = blockIdx.x * 8 + (tid >> 5);
    const int gwn = gridDim.x * 8;

    // step 1: Tx1 = prop(h); out += coe1 * Tx1
    {
        const float2* v2 = (const float2*)g_buf0;
        float c1 = s_coe[1];
        for (int dst0 = gw * 4; dst0 < n; dst0 += gwn * 4) {
            #pragma unroll
            for (int t = 0; t < 4; t++) {
                int dst = dst0 + t;
                if (dst >= n) break;
                int s = g_rowptr[dst], e2 = g_rowptr[dst + 1];
                float ax = 0.f, ay = 0.f;
                prop_accum(v2, s, e2, lane, ax, ay);
                int idx = dst * 32 + lane;
                ((float2*)g_buf1)[idx] = make_float2(ax, ay);
                float2 o = out[idx];
                o.x = fmaf(c1, ax, o.x);
                o.y = fmaf(c1, ay, o.y);
                out[idx] = o;
            }
        }
    }
    // steps 2..K
    int i0 = 0, i1 = 1;
    for (int i = 2; i <= KCH; i++) {
        gbar();
        int i2 = 3 - i0 - i1;
        const float2* v2 = (const float2*)bufptr(i1);
        const float2* t0 = (const float2*)bufptr(i0);
        float2* t2 = (float2*)bufptr(i2);
        float coe = s_coe[i];
        for (int dst0 = gw * 4; dst0 < n; dst0 += gwn * 4) {
            #pragma unroll
            for (int t = 0; t < 4; t++) {
                int dst = dst0 + t;
                if (dst >= n) break;
                int s = g_rowptr[dst], e2 = g_rowptr[dst + 1];
                float ax = 0.f, ay = 0.f;
                prop_accum(v2, s, e2, lane, ax, ay);
                int idx = dst * 32 + lane;
                float2 p0 = t0[idx];
                float2 nt = make_float2(2.f * ax - p0.x, 2.f * ay - p0.y);
                t2[idx] = nt;
                float2 o = out[idx];
                o.x = fmaf(coe, nt.x, o.x);
                o.y = fmaf(coe, nt.y, o.y);
                out[idx] = o;
            }
        }
        i0 = i1; i1 = i2;
    }
}

// ---------------- launch ------------------------------------------------------
extern "C" void kernel_launch(void* const* d_in, const int* in_sizes, int n_in,
                              void* d_out, int out_size)
{
    const float* x    = (const float*)d_in[0];
    const int*   ei   = (const int*)d_in[1];
    const float* W1   = (const float*)d_in[2];
    const float* b1   = (const float*)d_in[3];
    const float* W2   = (const float*)d_in[4];
    const float* b2   = (const float*)d_in[5];
    const float* temp = (const float*)d_in[6];
    float*       out  = (float*)d_out;

    int n = in_sizes[0] / FIN;   // 100000
    int e = in_sizes[1] / 2;     // 1600000

    static int attr_done = 0;
    if (!attr_done) {
        cudaFuncSetAttribute(mlp_tc_main,
                             cudaFuncAttributeMaxDynamicSharedMemorySize, SMEM_MLP);
        attr_done = 1;
    }

    mlp_tc_main<<<(n + 127) / 128, 256, SMEM_MLP>>>(x, W1, b1, W2, b2, temp, n, out);
    prep_prop_persist<<<PGRID, 256>>>(ei, temp, e, n, (float2*)out);
}

// round 14
// speedup vs baseline: 1.2490x; 1.0694x over previous
#include <cuda_runtime.h>
#include <cuda_fp16.h>
#include <math.h>
#include <stdint.h>

// Problem constants (fixed shapes per reference)
#define NMAX 100000
#define EMAX 1600000
#define FIN  256
#define HID  64
#define KCH  10
#define SP   72          // fp16 smem row stride (144B, LDSM conflict-free)
#define PGRID 296        // 2 blocks/SM x 148 SMs, co-resident by launch_bounds

// ---------------- static device scratch (no allocations allowed) -------------
__device__ float g_buf0[NMAX * HID];
__device__ float g_buf1[NMAX * HID];
__device__ float g_buf2[NMAX * HID];

__device__ int   g_deg[NMAX];
__device__ int   g_cnt[NMAX];
__device__ float g_dis[NMAX];
__device__ int   g_excl[NMAX];
__device__ int   g_rowptr[NMAX + 1];
__device__ int   g_cursor[NMAX];
__device__ int   g_blksum[256];
__device__ int2  g_csr[EMAX];          // packed {src, float_as_int(w)}

// global barrier state (only touched in non-skip path)
__device__ volatile unsigned g_gen;
__device__ unsigned g_cntbar;

// Chebyshev nodes x_j = cos((10.5-j)pi/11) (roots of T11), full double precision.
__constant__ double c_seed[KCH + 1] = {
    -0.9898214418809327, -0.9096319953545184, -0.7557495743542583,
    -0.5406408174555976, -0.2817325568414297, 0.0,
     0.2817325568414297,  0.5406408174555976, 0.7557495743542583,
     0.9096319953545184,  0.9898214418809327
};

__device__ __forceinline__ float* bufptr(int i) {
    return (i == 0) ? g_buf0 : ((i == 1) ? g_buf1 : g_buf2);
}

// sense-reversing grid barrier; all blocks of the (co-resident) grid must call.
__device__ __forceinline__ void gbar() {
    __syncthreads();
    if (threadIdx.x == 0) {
        unsigned gen = g_gen;
        __threadfence();
        if (atomicAdd(&g_cntbar, 1u) == gridDim.x - 1) {
            g_cntbar = 0;
            __threadfence();
            g_gen = gen + 1;
        } else {
            while (g_gen == gen) { __nanosleep(32); }
            __threadfence();
        }
    }
    __syncthreads();
}

// ---------------- per-warp Chebyshev coefficients (deterministic) ------------
// Lane j: T_i(x_j) by double recurrence from exact-node constants, times
// temp[j]; smem reduce. coe_i = 2/11 * sum_j acc_i.
// skip iff sum_{i>=1}|coe_i| < 1e-8 (dropping propagation then bounds the
// norm error by ~1e-6 relative — 3 orders under the 1e-3 threshold).
// Deterministic & identical on every block -> identical skip decision.
__device__ void warp_coef2(const float* __restrict__ temp,
                           float* s_coe, int* s_skip, int lane)
{
    __shared__ double sred[KCH + 1][KCH + 2];
    double tj = 0.0, x = 0.0;
    if (lane <= KCH) {
        tj = (double)temp[lane];
        x = c_seed[lane];
    }
    double acc[KCH + 1];
    {
        double t0 = 1.0, t1 = x;
        acc[0] = tj;
        acc[1] = x * tj;
        #pragma unroll
        for (int i = 2; i <= KCH; i++) {
            double t2 = 2.0 * x * t1 - t0;
            acc[i] = t2 * tj;
            t0 = t1; t1 = t2;
        }
    }
    if (lane <= KCH) {
        #pragma unroll
        for (int i = 0; i <= KCH; i++) sred[i][lane] = acc[i];
    }
    __syncwarp();
    double c = 0.0;
    if (lane <= KCH) {
        #pragma unroll
        for (int j = 0; j <= KCH; j++) c += sred[lane][j];
        c *= 2.0 / (double)(KCH + 1);
        s_coe[lane] = (float)c;
    }
    double a = (lane >= 1 && lane <= KCH) ? fabs(c) : 0.0;
    #pragma unroll
    for (int off = 16; off > 0; off >>= 1)
        a += __shfl_down_sync(0xffffffffu, a, off);
    if (lane == 0) *s_skip = (a < 1e-8) ? 1 : 0;
    __syncwarp();
}

// ---------------- tensor-core helpers ----------------------------------------
__device__ __forceinline__ uint32_t smem_u32(const void* p) {
    return (uint32_t)__cvta_generic_to_shared(p);
}
__device__ __forceinline__ void ldsm4(uint32_t r[4], uint32_t a) {
    asm volatile("ldmatrix.sync.aligned.m8n8.x4.shared.b16 {%0,%1,%2,%3},[%4];"
        : "=r"(r[0]), "=r"(r[1]), "=r"(r[2]), "=r"(r[3]) : "r"(a));
}
__device__ __forceinline__ void ldsm4t(uint32_t r[4], uint32_t a) {
    asm volatile("ldmatrix.sync.aligned.m8n8.x4.trans.shared.b16 {%0,%1,%2,%3},[%4];"
        : "=r"(r[0]), "=r"(r[1]), "=r"(r[2]), "=r"(r[3]) : "r"(a));
}
__device__ __forceinline__ void mma_f16(float c[4], const uint32_t a[4],
                                        uint32_t b0, uint32_t b1) {
    asm volatile("mma.sync.aligned.m16n8k16.row.col.f32.f16.f16.f32 "
        "{%0,%1,%2,%3},{%4,%5,%6,%7},{%8,%9},{%0,%1,%2,%3};"
        : "+f"(c[0]), "+f"(c[1]), "+f"(c[2]), "+f"(c[3])
        : "r"(a[0]), "r"(a[1]), "r"(a[2]), "r"(a[3]), "r"(b0), "r"(b1));
}
__device__ __forceinline__ uint32_t pack_h2(float2 v) {
    union { __half2 h; uint32_t u; } p;
    p.h = __floats2half2_rn(v.x, v.y);
    return p.u;
}
__device__ __forceinline__ void pack_store(__half* dst, float4 v) {
    union { __half2 h[2]; uint2 u; } p;
    p.h[0] = __floats2half2_rn(v.x, v.y);
    p.h[1] = __floats2half2_rn(v.z, v.w);
    *(uint2*)dst = p.u;
}

// ---------------- CSR edge accumulation --------------------------------------
__device__ __forceinline__ void prop_accum(const float2* __restrict__ v2,
                                           int s, int e, int lane,
                                           float& ax, float& ay)
{
    int i = s;
    for (; i + 4 <= e; i += 4) {
        int2 e0 = g_csr[i + 0], e1 = g_csr[i + 1];
        int2 e2 = g_csr[i + 2], e3 = g_csr[i + 3];
        float2 x0 = v2[e0.x * 32 + lane];
        float2 x1 = v2[e1.x * 32 + lane];
        float2 x2 = v2[e2.x * 32 + lane];
        float2 x3 = v2[e3.x * 32 + lane];
        float w0 = __int_as_float(e0.y), w1 = __int_as_float(e1.y);
        float w2 = __int_as_float(e2.y), w3 = __int_as_float(e3.y);
        ax = fmaf(w0, x0.x, ax); ay = fmaf(w0, x0.y, ay);
        ax = fmaf(w1, x1.x, ax); ay = fmaf(w1, x1.y, ay);
        ax = fmaf(w2, x2.x, ax); ay = fmaf(w2, x2.y, ay);
        ax = fmaf(w3, x3.x, ax); ay = fmaf(w3, x3.y, ay);
    }
    for (; i < e; i++) {
        int2 e0 = g_csr[i];
        float w0 = __int_as_float(e0.y);
        float2 x0 = v2[e0.x * 32 + lane];
        ax = fmaf(w0, x0.x, ax); ay = fmaf(w0, x0.y, ay);
    }
}

// ---------------- fully fused persistent kernel ------------------------------
// Phase A (always): MLP over tile-strided 128-row tiles.
//   out = (coe0/2)*h; g_buf0 = h. W1/W2 staged ONCE per block.
// Phase B (only if !skip): grid-barriered prep (degree/scan/scatter) + 10-step
//   Chebyshev propagation. Skip path exits before any gbar.
#define SM_W1 0
#define SM_W2 (256 * SP * 2)                 // 36864
#define SM_H  (SM_W2 + 64 * SP * 2)          // 46080
#define SMEM_MLP (SM_H + 128 * SP * 2)       // 64512

__global__ __launch_bounds__(256, 2) void fused_kernel(
    const float* __restrict__ x,
    const float* __restrict__ W1, const float* __restrict__ b1,
    const float* __restrict__ W2, const float* __restrict__ b2,
    const float* __restrict__ temp, const int* __restrict__ ei,
    int n, int e, float* __restrict__ out)
{
    extern __shared__ char sm[];
    __half* sW1 = (__half*)(sm + SM_W1);   // [256][SP] k-major
    __half* sW2 = (__half*)(sm + SM_W2);   // [64][SP]  k-major
    __half* sH  = (__half*)(sm + SM_H);    // [128][SP] per-warp strips
    __shared__ float s_coe[KCH + 1];
    __shared__ int   s_skip;
    __shared__ int wsum[8];
    __shared__ int s2[256];

    const int tid = threadIdx.x, lane = tid & 31, warp = tid >> 5;
    const int m0 = warp * 16;

    // warp 0: coefficients (overlaps W staging done by all warps below)
    if (tid < 32) warp_coef2(temp, s_coe, &s_skip, tid);

    // ---- stage W1 [256][64] and W2 [64][64] fp32 -> fp16 smem (ONCE) --------
    {
        #pragma unroll
        for (int it = 0; it < 16; it++) {
            int f = tid + it * 256;            // float4 index, 4096 total
            int kr = f >> 4, n4 = (f & 15) * 4;
            pack_store(sW1 + kr * SP + n4, *(const float4*)(W1 + (size_t)kr * HID + n4));
        }
        #pragma unroll
        for (int it = 0; it < 4; it++) {
            int f = tid + it * 256;            // 1024 total
            int kr = f >> 4, n4 = (f & 15) * 4;
            pack_store(sW2 + kr * SP + n4, *(const float4*)(W2 + (size_t)kr * HID + n4));
        }
    }
    __syncthreads();   // W + coefficients ready

    const float c0h = 0.5f * s_coe[0];
    const int skip = s_skip;

    // B ldsm4t lane addressing (k-major smem)
    const int brow = (lane & 7) + ((lane >> 3) & 1) * 8;
    const int bcol = (lane >> 4) * 8;
    const uint32_t bW1 = smem_u32(sW1) + (uint32_t)(brow * SP + bcol) * 2;
    const uint32_t bW2 = smem_u32(sW2) + (uint32_t)(brow * SP + bcol) * 2;

    // per-warp strip (X staging during GEMM1, H afterwards)
    __half* strip = sH + (size_t)m0 * SP;
    const uint32_t aBase = smem_u32(strip + (size_t)(lane & 15) * SP)
                           + (uint32_t)(lane >> 4) * 16;

    const int g = lane >> 2, tq = lane & 3;
    const float2* b1f2 = (const float2*)b1;
    const float2* b2f2 = (const float2*)b2;

    // ---- Phase A: MLP over tiles (tile-strided persistent loop) -------------
    const int ntiles = (n + 127) / 128;
    for (int tile = blockIdx.x; tile < ntiles; tile += gridDim.x) {
        const int row0 = tile * 128;
        const float* xw = x + (size_t)(row0 + m0) * FIN + lane * 2;
        const int vrows = min(16, max(0, n - (row0 + m0)));

        float c1[8][4];
        #pragma unroll
        for (int i = 0; i < 8; i++)
            #pragma unroll
            for (int j = 0; j < 4; j++) c1[i][j] = 0.f;

        // GEMM1: K=256 in 4 chunks of 64; warp-local staging
        #pragma unroll
        for (int c = 0; c < 4; c++) {
            float2 v[16];
            if (vrows == 16) {
                #pragma unroll
                for (int r = 0; r < 16; r++)
                    v[r] = *(const float2*)(xw + (size_t)r * FIN + c * 64);
            } else {
                #pragma unroll
                for (int r = 0; r < 16; r++)
                    v[r] = (r < vrows) ? *(const float2*)(xw + (size_t)r * FIN + c * 64)
                                       : make_float2(0.f, 0.f);
            }
            #pragma unroll
            for (int r = 0; r < 16; r++)
                *(uint32_t*)((char*)(strip + (size_t)r * SP + lane * 2)) = pack_h2(v[r]);
            __syncwarp();
            #pragma unroll
            for (int ks = 0; ks < 4; ks++) {
                uint32_t a[4];
                ldsm4(a, aBase + ks * 32);
                uint32_t kadd = (uint32_t)((c * 64 + ks * 16) * SP) * 2;
                #pragma unroll
                for (int ntp = 0; ntp < 4; ntp++) {
                    uint32_t b[4];
                    ldsm4t(b, bW1 + kadd + ntp * 32);
                    mma_f16(c1[2 * ntp],     a, b[0], b[1]);
                    mma_f16(c1[2 * ntp + 1], a, b[2], b[3]);
                }
            }
            __syncwarp();   // strip reuse fence
        }

        // H = relu(c1 + b1) -> own strip
        #pragma unroll
        for (int nt = 0; nt < 8; nt++) {
            float2 bb = b1f2[nt * 4 + tq];
            int col = nt * 8 + tq * 2;
            float v0h = fmaxf(c1[nt][0] + bb.x, 0.f);
            float v1h = fmaxf(c1[nt][1] + bb.y, 0.f);
            float v2h = fmaxf(c1[nt][2] + bb.x, 0.f);
            float v3h = fmaxf(c1[nt][3] + bb.y, 0.f);
            *(__half2*)(strip + (size_t)g * SP + col)       = __floats2half2_rn(v0h, v1h);
            *(__half2*)(strip + (size_t)(g + 8) * SP + col) = __floats2half2_rn(v2h, v3h);
        }
        __syncwarp();

        // GEMM2: H[16][64] @ W2
        float c2[8][4];
        #pragma unroll
        for (int i = 0; i < 8; i++)
            #pragma unroll
            for (int j = 0; j < 4; j++) c2[i][j] = 0.f;

        #pragma unroll
        for (int ks = 0; ks < 4; ks++) {
            uint32_t a[4];
            ldsm4(a, aBase + ks * 32);
            uint32_t kadd = (uint32_t)(ks * 16 * SP) * 2;
            #pragma unroll
            for (int ntp = 0; ntp < 4; ntp++) {
                uint32_t b[4];
                ldsm4t(b, bW2 + kadd + ntp * 32);
                mma_f16(c2[2 * ntp],     a, b[0], b[1]);
                mma_f16(c2[2 * ntp + 1], a, b[2], b[3]);
            }
        }
        __syncwarp();   // strip (H) fully consumed before next tile overwrites

        // epilogue
        #pragma unroll
        for (int nt = 0; nt < 8; nt++) {
            float2 bb = b2f2[nt * 4 + tq];
            int col = nt * 8 + tq * 2;
            int r0 = row0 + m0 + g, r1 = r0 + 8;
            if (r0 < n) {
                float2 h2 = make_float2(c2[nt][0] + bb.x, c2[nt][1] + bb.y);
                *(float2*)(g_buf0 + (size_t)r0 * HID + col) = h2;
                *(float2*)(out + (size_t)r0 * HID + col) = make_float2(c0h * h2.x, c0h * h2.y);
            }
            if (r1 < n) {
                float2 h2 = make_float2(c2[nt][2] + bb.x, c2[nt][3] + bb.y);
                *(float2*)(g_buf0 + (size_t)r1 * HID + col) = h2;
                *(float2*)(out + (size_t)r1 * HID + col) = make_float2(c0h * h2.x, c0h * h2.y);
            }
        }
    }

    if (skip) return;   // deterministic per-block: no gbar touched on skip path

    // ---- Phase B: preprocessing (grid-barriered) ----------------------------
    const int gtid = blockIdx.x * 256 + tid;
    const int gsz = gridDim.x * 256;

    gbar();   // all MLP tiles (g_buf0, out) complete grid-wide
    for (int i = gtid; i < n; i += gsz) { g_deg[i] = 0; g_cnt[i] = 0; }
    gbar();
    for (int i = gtid; i < e; i += gsz) {
        int r = ei[i];
        int c = ei[(size_t)e + i];
        if ((unsigned)r < (unsigned)n) atomicAdd(&g_deg[r], 1);
        if ((unsigned)c < (unsigned)n) atomicAdd(&g_cnt[c], 1);
    }
    gbar();
    int nchunk = (n + 1023) >> 10;
    for (int chunk = blockIdx.x; chunk < nchunk; chunk += gridDim.x) {
        int wid = tid >> 5;
        int base = chunk * 1024 + tid * 4;
        int v[4];
        #pragma unroll
        for (int j = 0; j < 4; j++) {
            int idx = base + j;
            v[j] = (idx < n) ? g_cnt[idx] : 0;
            if (idx < n) {
                int d = g_deg[idx];
                g_dis[idx] = (d > 0) ? rsqrtf((float)d) : 0.f;
            }
        }
        int tsum = v[0] + v[1] + v[2] + v[3];
        int sc = tsum;
        #pragma unroll
        for (int off = 1; off < 32; off <<= 1) {
            int t = __shfl_up_sync(0xffffffffu, sc, off);
            if (lane >= off) sc += t;
        }
        if (lane == 31) wsum[wid] = sc;
        __syncthreads();
        if (tid == 0) {
            int a = 0;
            #pragma unroll
            for (int i = 0; i < 8; i++) { int t = wsum[i]; wsum[i] = a; a += t; }
        }
        __syncthreads();
        int run = (sc - tsum) + wsum[wid];
        #pragma unroll
        for (int j = 0; j < 4; j++) {
            if (base + j < n) g_excl[base + j] = run;
            run += v[j];
        }
        if (tid == 255) g_blksum[chunk] = run;
        __syncthreads();
    }
    gbar();
    if (blockIdx.x == 0) {
        if (tid < nchunk) s2[tid] = g_blksum[tid];
        __syncthreads();
        if (tid == 0) {
            int a = 0;
            for (int i = 0; i < nchunk; i++) { int t = s2[i]; s2[i] = a; a += t; }
        }
        __syncthreads();
        if (tid < nchunk) g_blksum[tid] = s2[tid];
    }
    gbar();
    for (int i = gtid; i < n; i += gsz) {
        int v = g_excl[i] + g_blksum[i >> 10];
        g_rowptr[i] = v;
        g_cursor[i] = v;
    }
    if (gtid == 0) g_rowptr[n] = e;
    gbar();
    for (int i = gtid; i < e; i += gsz) {
        int r = ei[i];
        int c = ei[(size_t)e + i];
        if ((unsigned)r >= (unsigned)n || (unsigned)c >= (unsigned)n) continue;
        float w = -g_dis[r] * g_dis[c];
        int pos = atomicAdd(&g_cursor[c], 1);
        g_csr[pos] = make_int2(r, __float_as_int(w));
    }
    gbar();

    // ---- propagation: Chebyshev recurrence ----------------------------------
    float2* out2 = (float2*)out;
    const int gw = blockIdx.x * 8 + warp;
    const int gwn = gridDim.x * 8;

    {
        const float2* v2 = (const float2*)g_buf0;
        float c1c = s_coe[1];
        for (int dst0 = gw * 4; dst0 < n; dst0 += gwn * 4) {
            #pragma unroll
            for (int t = 0; t < 4; t++) {
                int dst = dst0 + t;
                if (dst >= n) break;
                int s = g_rowptr[dst], e2 = g_rowptr[dst + 1];
                float ax = 0.f, ay = 0.f;
                prop_accum(v2, s, e2, lane, ax, ay);
                int idx = dst * 32 + lane;
                ((float2*)g_buf1)[idx] = make_float2(ax, ay);
                float2 o = out2[idx];
                o.x = fmaf(c1c, ax, o.x);
                o.y = fmaf(c1c, ay, o.y);
                out2[idx] = o;
            }
        }
    }
    int i0 = 0, i1 = 1;
    for (int i = 2; i <= KCH; i++) {
        gbar();
        int i2 = 3 - i0 - i1;
        const float2* v2 = (const float2*)bufptr(i1);
        const float2* t0 = (const float2*)bufptr(i0);
        float2* t2 = (float2*)bufptr(i2);
        float coe = s_coe[i];
        for (int dst0 = gw * 4; dst0 < n; dst0 += gwn * 4) {
            #pragma unroll
            for (int t = 0; t < 4; t++) {
                int dst = dst0 + t;
                if (dst >= n) break;
                int s = g_rowptr[dst], e2 = g_rowptr[dst + 1];
                float ax = 0.f, ay = 0.f;
                prop_accum(v2, s, e2, lane, ax, ay);
                int idx = dst * 32 + lane;
                float2 p0 = t0[idx];
                float2 nt = make_float2(2.f * ax - p0.x, 2.f * ay - p0.y);
                t2[idx] = nt;
                float2 o = out2[idx];
                o.x = fmaf(coe, nt.x, o.x);
                o.y = fmaf(coe, nt.y, o.y);
                out2[idx] = o;
            }
        }
        i0 = i1; i1 = i2;
    }
}

// ---------------- launch ------------------------------------------------------
extern "C" void kernel_launch(void* const* d_in, const int* in_sizes, int n_in,
                              void* d_out, int out_size)
{
    const float* x    = (const float*)d_in[0];
    const int*   ei   = (const int*)d_in[1];
    const float* W1   = (const float*)d_in[2];
    const float* b1   = (const float*)d_in[3];
    const float* W2   = (const float*)d_in[4];
    const float* b2   = (const float*)d_in[5];
    const float* temp = (const float*)d_in[6];
    float*       out  = (float*)d_out;

    int n = in_sizes[0] / FIN;   // 100000
    int e = in_sizes[1] / 2;     // 1600000

    cudaFuncSetAttribute(fused_kernel,
                         cudaFuncAttributeMaxDynamicSharedMemorySize, SMEM_MLP);
    fused_kernel<<<PGRID, 256, SMEM_MLP>>>(x, W1, b1, W2, b2, temp, ei, n, e, out);
}

// round 15
// speedup vs baseline: 1.4024x; 1.1228x over previous
#include <cuda_runtime.h>
#include <cuda_fp16.h>
#include <math.h>
#include <stdint.h>

// Problem constants (fixed shapes per reference)
#define NMAX 100000
#define EMAX 1600000
#define FIN  256
#define HID  64
#define KCH  10
#define SP   72          // fp16 smem row stride (144B, LDSM conflict-free)
#define PGRID 296        // 2 blocks/SM x 148 SMs, co-resident by launch_bounds

// ---------------- static device scratch (no allocations allowed) -------------
__device__ float g_buf0[NMAX * HID];
__device__ float g_buf1[NMAX * HID];
__device__ float g_buf2[NMAX * HID];

__device__ int   g_deg[NMAX];
__device__ int   g_cnt[NMAX];
__device__ float g_dis[NMAX];
__device__ int   g_excl[NMAX];
__device__ int   g_rowptr[NMAX + 1];
__device__ int   g_cursor[NMAX];
__device__ int   g_blksum[256];
__device__ int2  g_csr[EMAX];          // packed {src, float_as_int(w)}

// global barrier state (only touched in non-skip path)
__device__ volatile unsigned g_gen;
__device__ unsigned g_cntbar;

// Chebyshev nodes x_j = cos((10.5-j)pi/11) (roots of T11), full double precision.
__constant__ double c_seed[KCH + 1] = {
    -0.9898214418809327, -0.9096319953545184, -0.7557495743542583,
    -0.5406408174555976, -0.2817325568414297, 0.0,
     0.2817325568414297,  0.5406408174555976, 0.7557495743542583,
     0.9096319953545184,  0.9898214418809327
};

__device__ __forceinline__ float* bufptr(int i) {
    return (i == 0) ? g_buf0 : ((i == 1) ? g_buf1 : g_buf2);
}

// sense-reversing grid barrier; all blocks of the (co-resident) grid must call.
__device__ __forceinline__ void gbar() {
    __syncthreads();
    if (threadIdx.x == 0) {
        unsigned gen = g_gen;
        __threadfence();
        if (atomicAdd(&g_cntbar, 1u) == gridDim.x - 1) {
            g_cntbar = 0;
            __threadfence();
            g_gen = gen + 1;
        } else {
            while (g_gen == gen) { __nanosleep(32); }
            __threadfence();
        }
    }
    __syncthreads();
}

// ---------------- per-warp Chebyshev coefficients (deterministic) ------------
// skip iff sum_{i>=1}|coe_i| < 1e-8 (dropping propagation then bounds the
// norm error by ~1e-6 relative). Deterministic & identical on every block.
__device__ void warp_coef2(const float* __restrict__ temp,
                           float* s_coe, int* s_skip, int lane)
{
    __shared__ double sred[KCH + 1][KCH + 2];
    double tj = 0.0, x = 0.0;
    if (lane <= KCH) {
        tj = (double)temp[lane];
        x = c_seed[lane];
    }
    double acc[KCH + 1];
    {
        double t0 = 1.0, t1 = x;
        acc[0] = tj;
        acc[1] = x * tj;
        #pragma unroll
        for (int i = 2; i <= KCH; i++) {
            double t2 = 2.0 * x * t1 - t0;
            acc[i] = t2 * tj;
            t0 = t1; t1 = t2;
        }
    }
    if (lane <= KCH) {
        #pragma unroll
        for (int i = 0; i <= KCH; i++) sred[i][lane] = acc[i];
    }
    __syncwarp();
    double c = 0.0;
    if (lane <= KCH) {
        #pragma unroll
        for (int j = 0; j <= KCH; j++) c += sred[lane][j];
        c *= 2.0 / (double)(KCH + 1);
        s_coe[lane] = (float)c;
    }
    double a = (lane >= 1 && lane <= KCH) ? fabs(c) : 0.0;
    #pragma unroll
    for (int off = 16; off > 0; off >>= 1)
        a += __shfl_down_sync(0xffffffffu, a, off);
    if (lane == 0) *s_skip = (a < 1e-8) ? 1 : 0;
    __syncwarp();
}

// ---------------- tensor-core helpers ----------------------------------------
__device__ __forceinline__ uint32_t smem_u32(const void* p) {
    return (uint32_t)__cvta_generic_to_shared(p);
}
__device__ __forceinline__ void ldsm4(uint32_t r[4], uint32_t a) {
    asm volatile("ldmatrix.sync.aligned.m8n8.x4.shared.b16 {%0,%1,%2,%3},[%4];"
        : "=r"(r[0]), "=r"(r[1]), "=r"(r[2]), "=r"(r[3]) : "r"(a));
}
__device__ __forceinline__ void ldsm4t(uint32_t r[4], uint32_t a) {
    asm volatile("ldmatrix.sync.aligned.m8n8.x4.trans.shared.b16 {%0,%1,%2,%3},[%4];"
        : "=r"(r[0]), "=r"(r[1]), "=r"(r[2]), "=r"(r[3]) : "r"(a));
}
__device__ __forceinline__ void mma_f16(float c[4], const uint32_t a[4],
                                        uint32_t b0, uint32_t b1) {
    asm volatile("mma.sync.aligned.m16n8k16.row.col.f32.f16.f16.f32 "
        "{%0,%1,%2,%3},{%4,%5,%6,%7},{%8,%9},{%0,%1,%2,%3};"
        : "+f"(c[0]), "+f"(c[1]), "+f"(c[2]), "+f"(c[3])
        : "r"(a[0]), "r"(a[1]), "r"(a[2]), "r"(a[3]), "r"(b0), "r"(b1));
}
__device__ __forceinline__ void pack_store(__half* dst, float4 v) {
    union { __half2 h[2]; uint2 u; } p;
    p.h[0] = __floats2half2_rn(v.x, v.y);
    p.h[1] = __floats2half2_rn(v.z, v.w);
    *(uint2*)dst = p.u;
}

// ---------------- CSR edge accumulation --------------------------------------
__device__ __forceinline__ void prop_accum(const float2* __restrict__ v2,
                                           int s, int e, int lane,
                                           float& ax, float& ay)
{
    int i = s;
    for (; i + 4 <= e; i += 4) {
        int2 e0 = g_csr[i + 0], e1 = g_csr[i + 1];
        int2 e2 = g_csr[i + 2], e3 = g_csr[i + 3];
        float2 x0 = v2[e0.x * 32 + lane];
        float2 x1 = v2[e1.x * 32 + lane];
        float2 x2 = v2[e2.x * 32 + lane];
        float2 x3 = v2[e3.x * 32 + lane];
        float w0 = __int_as_float(e0.y), w1 = __int_as_float(e1.y);
        float w2 = __int_as_float(e2.y), w3 = __int_as_float(e3.y);
        ax = fmaf(w0, x0.x, ax); ay = fmaf(w0, x0.y, ay);
        ax = fmaf(w1, x1.x, ax); ay = fmaf(w1, x1.y, ay);
        ax = fmaf(w2, x2.x, ax); ay = fmaf(w2, x2.y, ay);
        ax = fmaf(w3, x3.x, ax); ay = fmaf(w3, x3.y, ay);
    }
    for (; i < e; i++) {
        int2 e0 = g_csr[i];
        float w0 = __int_as_float(e0.y);
        float2 x0 = v2[e0.x * 32 + lane];
        ax = fmaf(w0, x0.x, ax); ay = fmaf(w0, x0.y, ay);
    }
}

// ---------------- fully fused persistent kernel ------------------------------
// Phase A (always): MLP over tile-strided 128-row tiles.
//   out = (coe0/2)*h;  g_buf0 = h only if !skip. W1/W2 staged ONCE per block.
// Phase B (only if !skip): grid-barriered prep + 10-step Chebyshev propagation.
#define SM_W1 0
#define SM_W2 (256 * SP * 2)                 // 36864
#define SM_H  (SM_W2 + 64 * SP * 2)          // 46080
#define SMEM_MLP (SM_H + 128 * SP * 2)       // 64512

__global__ __launch_bounds__(256, 2) void fused_kernel(
    const float* __restrict__ x,
    const float* __restrict__ W1, const float* __restrict__ b1,
    const float* __restrict__ W2, const float* __restrict__ b2,
    const float* __restrict__ temp, const int* __restrict__ ei,
    int n, int e, float* __restrict__ out)
{
    extern __shared__ char sm[];
    __half* sW1 = (__half*)(sm + SM_W1);   // [256][SP] k-major
    __half* sW2 = (__half*)(sm + SM_W2);   // [64][SP]  k-major
    __half* sH  = (__half*)(sm + SM_H);    // [128][SP] per-warp strips
    __shared__ float s_coe[KCH + 1];
    __shared__ int   s_skip;
    __shared__ int wsum[8];
    __shared__ int s2[256];

    const int tid = threadIdx.x, lane = tid & 31, warp = tid >> 5;
    const int m0 = warp * 16;

    // warp 0: coefficients (overlaps W staging by all warps below)
    if (tid < 32) warp_coef2(temp, s_coe, &s_skip, tid);

    // ---- stage W1 [256][64] and W2 [64][64] fp32 -> fp16 smem (ONCE) --------
    {
        #pragma unroll
        for (int it = 0; it < 16; it++) {
            int f = tid + it * 256;            // float4 index, 4096 total
            int kr = f >> 4, n4 = (f & 15) * 4;
            pack_store(sW1 + kr * SP + n4, *(const float4*)(W1 + (size_t)kr * HID + n4));
        }
        #pragma unroll
        for (int it = 0; it < 4; it++) {
            int f = tid + it * 256;            // 1024 total
            int kr = f >> 4, n4 = (f & 15) * 4;
            pack_store(sW2 + kr * SP + n4, *(const float4*)(W2 + (size_t)kr * HID + n4));
        }
    }
    __syncthreads();   // W + coefficients ready

    const float c0h = 0.5f * s_coe[0];
    const int skip = s_skip;

    // B ldsm4t lane addressing (k-major smem)
    const int brow = (lane & 7) + ((lane >> 3) & 1) * 8;
    const int bcol = (lane >> 4) * 8;
    const uint32_t bW1 = smem_u32(sW1) + (uint32_t)(brow * SP + bcol) * 2;
    const uint32_t bW2 = smem_u32(sW2) + (uint32_t)(brow * SP + bcol) * 2;

    // per-warp strip (X staging during GEMM1, H afterwards)
    __half* strip = sH + (size_t)m0 * SP;
    const uint32_t aBase = smem_u32(strip + (size_t)(lane & 15) * SP)
                           + (uint32_t)(lane >> 4) * 16;

    // Wide A loader: half-warp h = lane>>4 covers row 2j+h; 16 lanes x float4
    // = one full 64-col row chunk per half-warp (LDG.128, 256B contiguous).
    const int rofs = lane >> 4;          // 0 or 1
    const int c4 = (lane & 15) * 4;      // col base within chunk
    const int g = lane >> 2, tq = lane & 3;
    const float2* b1f2 = (const float2*)b1;
    const float2* b2f2 = (const float2*)b2;

    // ---- Phase A: MLP over tiles (tile-strided persistent loop) -------------
    const int ntiles = (n + 127) / 128;
    for (int tile = blockIdx.x; tile < ntiles; tile += gridDim.x) {
        const int row0 = tile * 128;
        const float* xw = x + (size_t)(row0 + m0) * FIN + c4;
        const int vrows = min(16, max(0, n - (row0 + m0)));

        float c1[8][4];
        #pragma unroll
        for (int i = 0; i < 8; i++)
            #pragma unroll
            for (int j = 0; j < 4; j++) c1[i][j] = 0.f;

        // GEMM1: K=256 in 4 chunks of 64; warp-local staging (wide ld/st)
        #pragma unroll
        for (int c = 0; c < 4; c++) {
            float4 v[8];
            if (vrows == 16) {
                #pragma unroll
                for (int j = 0; j < 8; j++)
                    v[j] = *(const float4*)(xw + (size_t)(2 * j + rofs) * FIN + c * 64);
            } else {
                #pragma unroll
                for (int j = 0; j < 8; j++) {
                    int r = 2 * j + rofs;
                    v[j] = (r < vrows) ? *(const float4*)(xw + (size_t)r * FIN + c * 64)
                                       : make_float4(0.f, 0.f, 0.f, 0.f);
                }
            }
            #pragma unroll
            for (int j = 0; j < 8; j++)
                pack_store(strip + (size_t)(2 * j + rofs) * SP + c4, v[j]);
            __syncwarp();
            #pragma unroll
            for (int ks = 0; ks < 4; ks++) {
                uint32_t a[4];
                ldsm4(a, aBase + ks * 32);
                uint32_t kadd = (uint32_t)((c * 64 + ks * 16) * SP) * 2;
                #pragma unroll
                for (int ntp = 0; ntp < 4; ntp++) {
                    uint32_t b[4];
                    ldsm4t(b, bW1 + kadd + ntp * 32);
                    mma_f16(c1[2 * ntp],     a, b[0], b[1]);
                    mma_f16(c1[2 * ntp + 1], a, b[2], b[3]);
                }
            }
            __syncwarp();   // strip reuse fence
        }

        // H = relu(c1 + b1) -> own strip
        #pragma unroll
        for (int nt = 0; nt < 8; nt++) {
            float2 bb = b1f2[nt * 4 + tq];
            int col = nt * 8 + tq * 2;
            float v0h = fmaxf(c1[nt][0] + bb.x, 0.f);
            float v1h = fmaxf(c1[nt][1] + bb.y, 0.f);
            float v2h = fmaxf(c1[nt][2] + bb.x, 0.f);
            float v3h = fmaxf(c1[nt][3] + bb.y, 0.f);
            *(__half2*)(strip + (size_t)g * SP + col)       = __floats2half2_rn(v0h, v1h);
            *(__half2*)(strip + (size_t)(g + 8) * SP + col) = __floats2half2_rn(v2h, v3h);
        }
        __syncwarp();

        // GEMM2: H[16][64] @ W2
        float c2[8][4];
        #pragma unroll
        for (int i = 0; i < 8; i++)
            #pragma unroll
            for (int j = 0; j < 4; j++) c2[i][j] = 0.f;

        #pragma unroll
        for (int ks = 0; ks < 4; ks++) {
            uint32_t a[4];
            ldsm4(a, aBase + ks * 32);
            uint32_t kadd = (uint32_t)(ks * 16 * SP) * 2;
            #pragma unroll
            for (int ntp = 0; ntp < 4; ntp++) {
                uint32_t b[4];
                ldsm4t(b, bW2 + kadd + ntp * 32);
                mma_f16(c2[2 * ntp],     a, b[0], b[1]);
                mma_f16(c2[2 * ntp + 1], a, b[2], b[3]);
            }
        }
        __syncwarp();   // strip (H) fully consumed before next tile overwrites

        // epilogue: out = c0h*h2 always; g_buf0 = h2 only if !skip
        #pragma unroll
        for (int nt = 0; nt < 8; nt++) {
            float2 bb = b2f2[nt * 4 + tq];
            int col = nt * 8 + tq * 2;
            int r0 = row0 + m0 + g, r1 = r0 + 8;
            if (r0 < n) {
                float2 h2 = make_float2(c2[nt][0] + bb.x, c2[nt][1] + bb.y);
                if (!skip) *(float2*)(g_buf0 + (size_t)r0 * HID + col) = h2;
                *(float2*)(out + (size_t)r0 * HID + col) = make_float2(c0h * h2.x, c0h * h2.y);
            }
            if (r1 < n) {
                float2 h2 = make_float2(c2[nt][2] + bb.x, c2[nt][3] + bb.y);
                if (!skip) *(float2*)(g_buf0 + (size_t)r1 * HID + col) = h2;
                *(float2*)(out + (size_t)r1 * HID + col) = make_float2(c0h * h2.x, c0h * h2.y);
            }
        }
    }

    if (skip) return;   // deterministic per-block: no gbar touched on skip path

    // ---- Phase B: preprocessing (grid-barriered) ----------------------------
    const int gtid = blockIdx.x * 256 + tid;
    const int gsz = gridDim.x * 256;

    gbar();   // all MLP tiles (g_buf0, out) complete grid-wide
    for (int i = gtid; i < n; i += gsz) { g_deg[i] = 0; g_cnt[i] = 0; }
    gbar();
    for (int i = gtid; i < e; i += gsz) {
        int r = ei[i];
        int c = ei[(size_t)e + i];
        if ((unsigned)r < (unsigned)n) atomicAdd(&g_deg[r], 1);
        if ((unsigned)c < (unsigned)n) atomicAdd(&g_cnt[c], 1);
    }
    gbar();
    int nchunk = (n + 1023) >> 10;
    for (int chunk = blockIdx.x; chunk < nchunk; chunk += gridDim.x) {
        int wid = tid >> 5;
        int base = chunk * 1024 + tid * 4;
        int v[4];
        #pragma unroll
        for (int j = 0; j < 4; j++) {
            int idx = base + j;
            v[j] = (idx < n) ? g_cnt[idx] : 0;
            if (idx < n) {
                int d = g_deg[idx];
                g_dis[idx] = (d > 0) ? rsqrtf((float)d) : 0.f;
            }
        }
        int tsum = v[0] + v[1] + v[2] + v[3];
        int sc = tsum;
        #pragma unroll
        for (int off = 1; off < 32; off <<= 1) {
            int t = __shfl_up_sync(0xffffffffu, sc, off);
            if (lane >= off) sc += t;
        }
        if (lane == 31) wsum[wid] = sc;
        __syncthreads();
        if (tid == 0) {
            int a = 0;
            #pragma unroll
            for (int i = 0; i < 8; i++) { int t = wsum[i]; wsum[i] = a; a += t; }
        }
        __syncthreads();
        int run = (sc - tsum) + wsum[wid];
        #pragma unroll
        for (int j = 0; j < 4; j++) {
            if (base + j < n) g_excl[base + j] = run;
            run += v[j];
        }
        if (tid == 255) g_blksum[chunk] = run;
        __syncthreads();
    }
    gbar();
    if (blockIdx.x == 0) {
        if (tid < nchunk) s2[tid] = g_blksum[tid];
        __syncthreads();
        if (tid == 0) {
            int a = 0;
            for (int i = 0; i < nchunk; i++) { int t = s2[i]; s2[i] = a; a += t; }
        }
        __syncthreads();
        if (tid < nchunk) g_blksum[tid] = s2[tid];
    }
    gbar();
    for (int i = gtid; i < n; i += gsz) {
        int v = g_excl[i] + g_blksum[i >> 10];
        g_rowptr[i] = v;
        g_cursor[i] = v;
    }
    if (gtid == 0) g_rowptr[n] = e;
    gbar();
    for (int i = gtid; i < e; i += gsz) {
        int r = ei[i];
        int c = ei[(size_t)e + i];
        if ((unsigned)r >= (unsigned)n || (unsigned)c >= (unsigned)n) continue;
        float w = -g_dis[r] * g_dis[c];
        int pos = atomicAdd(&g_cursor[c], 1);
        g_csr[pos] = make_int2(r, __float_as_int(w));
    }
    gbar();

    // ---- propagation: Chebyshev recurrence ----------------------------------
    float2* out2 = (float2*)out;
    const int gw = blockIdx.x * 8 + warp;
    const int gwn = gridDim.x * 8;

    {
        const float2* v2 = (const float2*)g_buf0;
        float c1c = s_coe[1];
        for (int dst0 = gw * 4; dst0 < n; dst0 += gwn * 4) {
            #pragma unroll
            for (int t = 0; t < 4; t++) {
                int dst = dst0 + t;
                if (dst >= n) break;
                int s = g_rowptr[dst], e2 = g_rowptr[dst + 1];
                float ax = 0.f, ay = 0.f;
                prop_accum(v2, s, e2, lane, ax, ay);
                int idx = dst * 32 + lane;
                ((float2*)g_buf1)[idx] = make_float2(ax, ay);
                float2 o = out2[idx];
                o.x = fmaf(c1c, ax, o.x);
                o.y = fmaf(c1c, ay, o.y);
                out2[idx] = o;
            }
        }
    }
    int i0 = 0, i1 = 1;
    for (int i = 2; i <= KCH; i++) {
        gbar();
        int i2 = 3 - i0 - i1;
        const float2* v2 = (const float2*)bufptr(i1);
        const float2* t0 = (const float2*)bufptr(i0);
        float2* t2 = (float2*)bufptr(i2);
        float coe = s_coe[i];
        for (int dst0 = gw * 4; dst0 < n; dst0 += gwn * 4) {
            #pragma unroll
            for (int t = 0; t < 4; t++) {
                int dst = dst0 + t;
                if (dst >= n) break;
                int s = g_rowptr[dst], e2 = g_rowptr[dst + 1];
                float ax = 0.f, ay = 0.f;
                prop_accum(v2, s, e2, lane, ax, ay);
                int idx = dst * 32 + lane;
                float2 p0 = t0[idx];
                float2 nt = make_float2(2.f * ax - p0.x, 2.f * ay - p0.y);
                t2[idx] = nt;
                float2 o = out2[idx];
                o.x = fmaf(coe, nt.x, o.x);
                o.y = fmaf(coe, nt.y, o.y);
                out2[idx] = o;
            }
        }
        i0 = i1; i1 = i2;
    }
}

// ---------------- launch ------------------------------------------------------
extern "C" void kernel_launch(void* const* d_in, const int* in_sizes, int n_in,
                              void* d_out, int out_size)
{
    const float* x    = (const float*)d_in[0];
    const int*   ei   = (const int*)d_in[1];
    const float* W1   = (const float*)d_in[2];
    const float* b1   = (const float*)d_in[3];
    const float* W2   = (const float*)d_in[4];
    const float* b2   = (const float*)d_in[5];
    const float* temp = (const float*)d_in[6];
    float*       out  = (float*)d_out;

    int n = in_sizes[0] / FIN;   // 100000
    int e = in_sizes[1] / 2;     // 1600000

    cudaFuncSetAttribute(fused_kernel,
                         cudaFuncAttributeMaxDynamicSharedMemorySize, SMEM_MLP);
    fused_kernel<<<PGRID, 256, SMEM_MLP>>>(x, W1, b1, W2, b2, temp, ei, n, e, out);
}